// round 1
// baseline (speedup 1.0000x reference)
#include <cuda_runtime.h>
#include <cuda_bf16.h>
#include <math_constants.h>

#define Nn 50000
#define NF 256
#define NH 64
#define NC 40
#define NE 800000
#define NHW 80   // concat of the two 40-wide heads

// -------- device scratch (no allocs allowed) --------
__device__ float g_xw[(size_t)Nn * NH];    // x @ W1
__device__ float g_hacc[(size_t)Nn * NH];  // spmm1 accumulator
__device__ float g_hw[(size_t)Nn * NHW];   // relu(h) @ [W11|W12]
__device__ float g_zacc[(size_t)Nn * NHW]; // spmm2 accumulator (mean | logstd)

// ---------------- zero init ----------------
__global__ __launch_bounds__(256) void zero_acc() {
    size_t i = (size_t)blockIdx.x * blockDim.x + threadIdx.x;
    float4 z = make_float4(0.f, 0.f, 0.f, 0.f);
    if (i < (size_t)Nn * NH / 4)
        reinterpret_cast<float4*>(g_hacc)[i] = z;
    if (i < (size_t)Nn * NHW / 4)
        reinterpret_cast<float4*>(g_zacc)[i] = z;
}

// ---------------- GEMM1: xw = x @ W1  (50000x256 @ 256x64) ----------------
// Tile: BM=128, BK=32, BN=64(full). 256 threads, each computes 32 rows x 1 col.
__global__ __launch_bounds__(256) void gemm1(const float* __restrict__ x,
                                             const float* __restrict__ W1) {
    __shared__ float xs[128][32];  // 16KB
    __shared__ float ws[32][64];   // 8KB
    int tid = threadIdx.x;
    int m0 = blockIdx.x * 128;
    int c  = tid & 63;       // output column 0..63
    int tg = tid >> 6;       // row group 0..3 (constant within warp)

    float acc[32];
#pragma unroll
    for (int i = 0; i < 32; i++) acc[i] = 0.f;

    for (int k0 = 0; k0 < NF; k0 += 32) {
        // load x tile 128x32 (float4, coalesced)
#pragma unroll
        for (int p = 0; p < 4; p++) {
            int idx = tid + p * 256;       // float4 slot 0..1023
            int r   = idx >> 3;            // 8 float4 per row
            int kk  = (idx & 7) << 2;
            int row = m0 + r;
            float4 v = make_float4(0.f, 0.f, 0.f, 0.f);
            if (row < Nn)
                v = *reinterpret_cast<const float4*>(&x[(size_t)row * NF + k0 + kk]);
            *reinterpret_cast<float4*>(&xs[r][kk]) = v;
        }
        // load W tile 32x64 (float4, coalesced)
#pragma unroll
        for (int p = 0; p < 2; p++) {
            int idx = tid + p * 256;       // 0..511
            int kk  = idx >> 4;            // 16 float4 per row
            int cc  = (idx & 15) << 2;
            float4 v = *reinterpret_cast<const float4*>(&W1[(size_t)(k0 + kk) * NH + cc]);
            *reinterpret_cast<float4*>(&ws[kk][cc]) = v;
        }
        __syncthreads();
#pragma unroll
        for (int k4 = 0; k4 < 32; k4 += 4) {
            float w0 = ws[k4 + 0][c];
            float w1 = ws[k4 + 1][c];
            float w2 = ws[k4 + 2][c];
            float w3 = ws[k4 + 3][c];
#pragma unroll
            for (int i = 0; i < 32; i++) {
                float4 xv = *reinterpret_cast<float4*>(&xs[tg * 32 + i][k4]);
                acc[i] += xv.x * w0 + xv.y * w1 + xv.z * w2 + xv.w * w3;
            }
        }
        __syncthreads();
    }
#pragma unroll
    for (int i = 0; i < 32; i++) {
        int row = m0 + tg * 32 + i;
        if (row < Nn) g_xw[(size_t)row * NH + c] = acc[i];
    }
}

// ---------------- SpMM1: hacc[dst] += val * xw[src]  (64 feats) ----------------
__global__ __launch_bounds__(256) void spmm1(const int* __restrict__ src,
                                             const int* __restrict__ dst,
                                             const float* __restrict__ val) {
    int e = blockIdx.x * 8 + (threadIdx.x >> 5);
    if (e >= NE) return;
    int lane = threadIdx.x & 31;
    int s = src[e];
    int d = dst[e];
    float v = val[e];
    const float2* xr = reinterpret_cast<const float2*>(&g_xw[(size_t)s * NH]);
    float2 a = xr[lane];
    float* out = &g_hacc[(size_t)d * NH];
    atomicAdd(&out[lane * 2 + 0], v * a.x);
    atomicAdd(&out[lane * 2 + 1], v * a.y);
}

// ------- GEMM2: hw = relu(hacc + b1) @ [W11|W12]  (50000x64 @ 64x80) -------
// 320 threads: 32 rows per block, each thread = 1 of 80 cols x 8 rows.
__global__ __launch_bounds__(320) void gemm2(const float* __restrict__ b1,
                                             const float* __restrict__ W11,
                                             const float* __restrict__ W12) {
    __shared__ float hs[32][64];   // 8KB
    __shared__ float wt[80][68];   // transposed weights, padded stride (21.25KB)
    int tid = threadIdx.x;
    int r0 = blockIdx.x * 32;

    // load transposed concat weights: wt[j][k] = Wcat[k][j]
    for (int idx = tid; idx < 64 * 80; idx += 320) {
        int k = idx / 80;
        int j = idx % 80;
        float w = (j < NC) ? W11[(size_t)k * NC + j] : W12[(size_t)k * NC + (j - NC)];
        wt[j][k] = w;
    }
    // load h rows with bias + relu
    for (int idx = tid; idx < 32 * 64; idx += 320) {
        int r = idx >> 6;
        int k = idx & 63;
        int row = r0 + r;
        float hv = 0.f;
        if (row < Nn) hv = g_hacc[(size_t)row * NH + k] + b1[k];
        hs[r][k] = fmaxf(hv, 0.f);
    }
    __syncthreads();

    int j  = tid % 80;
    int rg = tid / 80;  // 0..3
    float acc[8];
#pragma unroll
    for (int i = 0; i < 8; i++) acc[i] = 0.f;
#pragma unroll
    for (int k = 0; k < 64; k += 4) {
        float4 w4 = *reinterpret_cast<float4*>(&wt[j][k]);
#pragma unroll
        for (int i = 0; i < 8; i++) {
            float4 h4 = *reinterpret_cast<float4*>(&hs[rg * 8 + i][k]);
            acc[i] += h4.x * w4.x + h4.y * w4.y + h4.z * w4.z + h4.w * w4.w;
        }
    }
#pragma unroll
    for (int i = 0; i < 8; i++) {
        int row = r0 + rg * 8 + i;
        if (row < Nn) g_hw[(size_t)row * NHW + j] = acc[i];
    }
}

// ---------------- SpMM2: zacc[dst] += val * hw[src]  (80 feats) ----------------
__global__ __launch_bounds__(256) void spmm2(const int* __restrict__ src,
                                             const int* __restrict__ dst,
                                             const float* __restrict__ val) {
    int e = blockIdx.x * 8 + (threadIdx.x >> 5);
    if (e >= NE) return;
    int lane = threadIdx.x & 31;
    int s = src[e];
    int d = dst[e];
    float v = val[e];
    const float2* hr = reinterpret_cast<const float2*>(&g_hw[(size_t)s * NHW]);
    float* out = &g_zacc[(size_t)d * NHW];
    float2 a = hr[lane];
    atomicAdd(&out[lane * 2 + 0], v * a.x);
    atomicAdd(&out[lane * 2 + 1], v * a.y);
    if (lane < 8) {
        float2 b = hr[32 + lane];
        atomicAdd(&out[64 + lane * 2 + 0], v * b.x);
        atomicAdd(&out[64 + lane * 2 + 1], v * b.y);
    }
}

// -------- finalize: z = eps*exp(logstd)+mean; out = log_softmax(z) --------
// one warp per row; lane covers class j=lane and (lane<8) j=32+lane
__global__ __launch_bounds__(256) void finalize(const float* __restrict__ eps,
                                                const float* __restrict__ b11,
                                                const float* __restrict__ b12,
                                                float* __restrict__ out) {
    int r = blockIdx.x * 8 + (threadIdx.x >> 5);
    if (r >= Nn) return;
    int lane = threadIdx.x & 31;
    const float* zr = &g_zacc[(size_t)r * NHW];

    float mean0 = zr[lane] + b11[lane];
    float ls0   = zr[NC + lane] + b12[lane];
    float z0 = eps[(size_t)r * NC + lane] * expf(ls0) + mean0;
    float z1 = -CUDART_INF_F;
    if (lane < 8) {
        int j = 32 + lane;
        float mean1 = zr[j] + b11[j];
        float ls1   = zr[NC + j] + b12[j];
        z1 = eps[(size_t)r * NC + j] * expf(ls1) + mean1;
    }
    float mx = fmaxf(z0, z1);
#pragma unroll
    for (int o = 16; o > 0; o >>= 1)
        mx = fmaxf(mx, __shfl_xor_sync(0xFFFFFFFFu, mx, o));
    float sm = expf(z0 - mx) + ((lane < 8) ? expf(z1 - mx) : 0.f);
#pragma unroll
    for (int o = 16; o > 0; o >>= 1)
        sm += __shfl_xor_sync(0xFFFFFFFFu, sm, o);
    float lse = logf(sm) + mx;
    out[(size_t)r * NC + lane] = z0 - lse;
    if (lane < 8)
        out[(size_t)r * NC + 32 + lane] = z1 - lse;
}

extern "C" void kernel_launch(void* const* d_in, const int* in_sizes, int n_in,
                              void* d_out, int out_size) {
    const float* x    = (const float*)d_in[0];
    const int*   esrc = (const int*)d_in[1];
    const int*   edst = (const int*)d_in[2];
    const float* evl  = (const float*)d_in[3];
    const float* eps  = (const float*)d_in[4];
    const float* W1   = (const float*)d_in[5];
    const float* b1   = (const float*)d_in[6];
    const float* W11  = (const float*)d_in[7];
    const float* b11  = (const float*)d_in[8];
    const float* W12  = (const float*)d_in[9];
    const float* b12  = (const float*)d_in[10];
    float* out = (float*)d_out;

    zero_acc<<<(Nn * NHW / 4 + 255) / 256, 256>>>();
    gemm1<<<(Nn + 127) / 128, 256>>>(x, W1);
    spmm1<<<NE / 8, 256>>>(esrc, edst, evl);
    gemm2<<<(Nn + 31) / 32, 320>>>(b1, W11, W12);
    spmm2<<<NE / 8, 256>>>(esrc, edst, evl);
    finalize<<<(Nn + 7) / 8, 256>>>(eps, b11, b12, out);
}

// round 2
// speedup vs baseline: 1.3271x; 1.3271x over previous
#include <cuda_runtime.h>
#include <cuda_bf16.h>
#include <math_constants.h>

#define Nn 50000
#define NF 256
#define NH 64
#define NC 40
#define NE 800000
#define NHW 80   // concat of the two 40-wide heads

// -------- device scratch (no allocs allowed) --------
__device__ float g_xw[(size_t)Nn * NH];    // x @ W1
__device__ float g_h[(size_t)Nn * NH];     // spmm1 result (pre-bias/relu)
__device__ float g_hw[(size_t)Nn * NHW];   // relu(h+b1) @ [W11|W12]
__device__ int   g_cnt[Nn];                // per-dst edge counts
__device__ int   g_rowptr[Nn + 1];         // CSR row offsets
__device__ int   g_cursor[Nn];             // scatter cursors
__device__ int2  g_pedge[NE];              // permuted (src, val-bits) by dst

// ---------------- zero counts ----------------
__global__ __launch_bounds__(256) void zero_cnt() {
    int i = blockIdx.x * 256 + threadIdx.x;
    if (i < Nn) g_cnt[i] = 0;
}

// ---------------- histogram of dst ----------------
__global__ __launch_bounds__(256) void hist(const int* __restrict__ dst) {
    int e = blockIdx.x * 256 + threadIdx.x;
    if (e < NE) atomicAdd(&g_cnt[dst[e]], 1);
}

// ---------------- single-block exclusive scan of g_cnt -> g_rowptr ----------------
__global__ __launch_bounds__(1024) void scan_k() {
    __shared__ int wsum[32];
    int tid = threadIdx.x, lane = tid & 31, w = tid >> 5;
    int running = 0;
    for (int base = 0; base < Nn; base += 1024) {
        int i = base + tid;
        int v = (i < Nn) ? g_cnt[i] : 0;
        int s = v;
#pragma unroll
        for (int o = 1; o < 32; o <<= 1) {
            int n = __shfl_up_sync(0xFFFFFFFFu, s, o);
            if (lane >= o) s += n;
        }
        if (lane == 31) wsum[w] = s;
        __syncthreads();
        if (w == 0) {
            int ws = wsum[lane];
#pragma unroll
            for (int o = 1; o < 32; o <<= 1) {
                int n = __shfl_up_sync(0xFFFFFFFFu, ws, o);
                if (lane >= o) ws += n;
            }
            wsum[lane] = ws;
        }
        __syncthreads();
        int woff = (w > 0) ? wsum[w - 1] : 0;
        int incl = running + woff + s;
        if (i < Nn) {
            g_rowptr[i] = incl - v;
            g_cursor[i] = incl - v;
        }
        running += wsum[31];
        __syncthreads();  // protect wsum reuse next iteration
    }
    if (tid == 0) g_rowptr[Nn] = running;
}

// ---------------- scatter edges into CSR order ----------------
__global__ __launch_bounds__(256) void scatter(const int* __restrict__ src,
                                               const int* __restrict__ dst,
                                               const float* __restrict__ val) {
    int e = blockIdx.x * 256 + threadIdx.x;
    if (e >= NE) return;
    int d = dst[e];
    int p = atomicAdd(&g_cursor[d], 1);
    g_pedge[p] = make_int2(src[e], __float_as_int(val[e]));
}

// ---------------- GEMM1: xw = x @ W1  (50000x256 @ 256x64) ----------------
__global__ __launch_bounds__(256) void gemm1(const float* __restrict__ x,
                                             const float* __restrict__ W1) {
    __shared__ float xs[128][32];  // 16KB
    __shared__ float ws[32][64];   // 8KB
    int tid = threadIdx.x;
    int m0 = blockIdx.x * 128;
    int c  = tid & 63;       // output column 0..63
    int tg = tid >> 6;       // row group 0..3

    float acc[32];
#pragma unroll
    for (int i = 0; i < 32; i++) acc[i] = 0.f;

    for (int k0 = 0; k0 < NF; k0 += 32) {
#pragma unroll
        for (int p = 0; p < 4; p++) {
            int idx = tid + p * 256;
            int r   = idx >> 3;
            int kk  = (idx & 7) << 2;
            int row = m0 + r;
            float4 v = make_float4(0.f, 0.f, 0.f, 0.f);
            if (row < Nn)
                v = *reinterpret_cast<const float4*>(&x[(size_t)row * NF + k0 + kk]);
            *reinterpret_cast<float4*>(&xs[r][kk]) = v;
        }
#pragma unroll
        for (int p = 0; p < 2; p++) {
            int idx = tid + p * 256;
            int kk  = idx >> 4;
            int cc  = (idx & 15) << 2;
            float4 v = *reinterpret_cast<const float4*>(&W1[(size_t)(k0 + kk) * NH + cc]);
            *reinterpret_cast<float4*>(&ws[kk][cc]) = v;
        }
        __syncthreads();
#pragma unroll
        for (int k4 = 0; k4 < 32; k4 += 4) {
            float w0 = ws[k4 + 0][c];
            float w1 = ws[k4 + 1][c];
            float w2 = ws[k4 + 2][c];
            float w3 = ws[k4 + 3][c];
#pragma unroll
            for (int i = 0; i < 32; i++) {
                float4 xv = *reinterpret_cast<float4*>(&xs[tg * 32 + i][k4]);
                acc[i] += xv.x * w0 + xv.y * w1 + xv.z * w2 + xv.w * w3;
            }
        }
        __syncthreads();
    }
#pragma unroll
    for (int i = 0; i < 32; i++) {
        int row = m0 + tg * 32 + i;
        if (row < Nn) g_xw[(size_t)row * NH + c] = acc[i];
    }
}

// ---------------- SpMM1 gather: h[r] = sum_e val*xw[src]  (64 feats) ----------------
__global__ __launch_bounds__(256) void spmm1g() {
    int r = blockIdx.x * 8 + (threadIdx.x >> 5);
    if (r >= Nn) return;
    int lane = threadIdx.x & 31;
    int e0 = g_rowptr[r], e1 = g_rowptr[r + 1];
    float ax = 0.f, ay = 0.f;
    for (int e = e0; e < e1; e++) {
        int2 ed = g_pedge[e];
        float v = __int_as_float(ed.y);
        float2 t = reinterpret_cast<const float2*>(&g_xw[(size_t)ed.x * NH])[lane];
        ax += v * t.x;
        ay += v * t.y;
    }
    reinterpret_cast<float2*>(&g_h[(size_t)r * NH])[lane] = make_float2(ax, ay);
}

// ------- GEMM2: hw = relu(h + b1) @ [W11|W12]  (50000x64 @ 64x80) -------
// 128 rows per block in 4 passes; weights loaded once per block.
__global__ __launch_bounds__(320) void gemm2(const float* __restrict__ b1,
                                             const float* __restrict__ W11,
                                             const float* __restrict__ W12) {
    __shared__ float hs[32][64];   // 8KB
    __shared__ float wt[80][68];   // transposed weights, padded (21.25KB)
    int tid = threadIdx.x;
    int r0 = blockIdx.x * 128;

    for (int idx = tid; idx < 64 * 80; idx += 320) {
        int k = idx / 80;
        int j = idx % 80;
        wt[j][k] = (j < NC) ? W11[(size_t)k * NC + j] : W12[(size_t)k * NC + (j - NC)];
    }
    int j  = tid % 80;
    int rg = tid / 80;  // 0..3

#pragma unroll
    for (int pass = 0; pass < 4; pass++) {
        int rbase = r0 + pass * 32;
        __syncthreads();
        for (int idx = tid; idx < 32 * 64; idx += 320) {
            int r = idx >> 6;
            int k = idx & 63;
            int row = rbase + r;
            float hv = 0.f;
            if (row < Nn) hv = g_h[(size_t)row * NH + k] + b1[k];
            hs[r][k] = fmaxf(hv, 0.f);
        }
        __syncthreads();

        float acc[8];
#pragma unroll
        for (int i = 0; i < 8; i++) acc[i] = 0.f;
#pragma unroll
        for (int k = 0; k < 64; k += 4) {
            float4 w4 = *reinterpret_cast<float4*>(&wt[j][k]);
#pragma unroll
            for (int i = 0; i < 8; i++) {
                float4 h4 = *reinterpret_cast<float4*>(&hs[rg * 8 + i][k]);
                acc[i] += h4.x * w4.x + h4.y * w4.y + h4.z * w4.z + h4.w * w4.w;
            }
        }
#pragma unroll
        for (int i = 0; i < 8; i++) {
            int row = rbase + rg * 8 + i;
            if (row < Nn) g_hw[(size_t)row * NHW + j] = acc[i];
        }
    }
}

// -- SpMM2 gather + finalize: z = eps*exp(logstd)+mean; out = log_softmax(z) --
// warp per row; 80 feats: lane -> float2 at [2*lane], lanes<8 also [64+2*lane]
__global__ __launch_bounds__(256) void spmm2fin(const float* __restrict__ eps,
                                                const float* __restrict__ b11,
                                                const float* __restrict__ b12,
                                                float* __restrict__ out) {
    __shared__ float zrow[8][80];
    int w = threadIdx.x >> 5;
    int lane = threadIdx.x & 31;
    int r = blockIdx.x * 8 + w;
    if (r >= Nn) return;

    int e0 = g_rowptr[r], e1 = g_rowptr[r + 1];
    float ax = 0.f, ay = 0.f, bx = 0.f, by = 0.f;
    for (int e = e0; e < e1; e++) {
        int2 ed = g_pedge[e];
        float v = __int_as_float(ed.y);
        const float2* hr = reinterpret_cast<const float2*>(&g_hw[(size_t)ed.x * NHW]);
        float2 t = hr[lane];
        ax += v * t.x;
        ay += v * t.y;
        if (lane < 8) {
            float2 u = hr[32 + lane];
            bx += v * u.x;
            by += v * u.y;
        }
    }
    zrow[w][lane * 2 + 0] = ax;
    zrow[w][lane * 2 + 1] = ay;
    if (lane < 8) {
        zrow[w][64 + lane * 2 + 0] = bx;
        zrow[w][64 + lane * 2 + 1] = by;
    }
    __syncwarp();

    const float* zr = zrow[w];
    float mean0 = zr[lane] + b11[lane];
    float ls0   = zr[NC + lane] + b12[lane];
    float z0 = eps[(size_t)r * NC + lane] * expf(ls0) + mean0;
    float z1 = -CUDART_INF_F;
    if (lane < 8) {
        int jj = 32 + lane;
        float mean1 = zr[jj] + b11[jj];
        float ls1   = zr[NC + jj] + b12[jj];
        z1 = eps[(size_t)r * NC + jj] * expf(ls1) + mean1;
    }
    float mx = fmaxf(z0, z1);
#pragma unroll
    for (int o = 16; o > 0; o >>= 1)
        mx = fmaxf(mx, __shfl_xor_sync(0xFFFFFFFFu, mx, o));
    float sm = expf(z0 - mx) + ((lane < 8) ? expf(z1 - mx) : 0.f);
#pragma unroll
    for (int o = 16; o > 0; o >>= 1)
        sm += __shfl_xor_sync(0xFFFFFFFFu, sm, o);
    float lse = logf(sm) + mx;
    out[(size_t)r * NC + lane] = z0 - lse;
    if (lane < 8)
        out[(size_t)r * NC + 32 + lane] = z1 - lse;
}

extern "C" void kernel_launch(void* const* d_in, const int* in_sizes, int n_in,
                              void* d_out, int out_size) {
    const float* x    = (const float*)d_in[0];
    const int*   esrc = (const int*)d_in[1];
    const int*   edst = (const int*)d_in[2];
    const float* evl  = (const float*)d_in[3];
    const float* eps  = (const float*)d_in[4];
    const float* W1   = (const float*)d_in[5];
    const float* b1   = (const float*)d_in[6];
    const float* W11  = (const float*)d_in[7];
    const float* b11  = (const float*)d_in[8];
    const float* W12  = (const float*)d_in[9];
    const float* b12  = (const float*)d_in[10];
    float* out = (float*)d_out;

    zero_cnt<<<(Nn + 255) / 256, 256>>>();
    hist<<<(NE + 255) / 256, 256>>>(edst);
    gemm1<<<(Nn + 127) / 128, 256>>>(x, W1);       // overlaps nothing (same stream) but independent
    scan_k<<<1, 1024>>>();
    scatter<<<(NE + 255) / 256, 256>>>(esrc, edst, evl);
    spmm1g<<<(Nn + 7) / 8, 256>>>();
    gemm2<<<(Nn + 127) / 128, 320>>>(b1, W11, W12);
    spmm2fin<<<(Nn + 7) / 8, 256>>>(eps, b11, b12, out);
}

// round 3
// speedup vs baseline: 1.4815x; 1.1163x over previous
#include <cuda_runtime.h>
#include <cuda_bf16.h>
#include <math_constants.h>

#define Nn 50000
#define NF 256
#define NH 64
#define NC 40
#define NE 800000
#define NHW 80   // concat of the two 40-wide heads

// -------- device scratch (no allocs allowed) --------
__device__ float g_xw[(size_t)Nn * NH];    // x @ W1
__device__ float g_h[(size_t)Nn * NH];     // spmm1 result (pre-bias/relu)
__device__ float g_hw[(size_t)Nn * NHW];   // relu(h+b1) @ [W11|W12]
__device__ int   g_cnt[Nn];                // per-dst edge counts
__device__ int   g_start[Nn];              // per-dst segment start (unsorted layout)
__device__ int   g_cursor[Nn];             // scatter cursors
__device__ int   g_total;                  // global segment allocator
__device__ int2  g_pedge[NE];              // permuted (src, val-bits) grouped by dst

// ---------------- zero counts + allocator ----------------
__global__ __launch_bounds__(256) void zero_cnt() {
    int i = blockIdx.x * 256 + threadIdx.x;
    if (i < Nn) g_cnt[i] = 0;
    if (i == 0) g_total = 0;
}

// ---------------- histogram of dst ----------------
__global__ __launch_bounds__(256) void hist(const int* __restrict__ dst) {
    int e = blockIdx.x * 256 + threadIdx.x;
    if (e < NE) atomicAdd(&g_cnt[dst[e]], 1);
}

// ------- segment assign: disjoint per-row ranges via warp scan + 1 atomic -------
__global__ __launch_bounds__(256) void assign_seg() {
    int i = blockIdx.x * 256 + threadIdx.x;
    int lane = threadIdx.x & 31;
    int c = (i < Nn) ? g_cnt[i] : 0;
    int s = c;
#pragma unroll
    for (int o = 1; o < 32; o <<= 1) {
        int n = __shfl_up_sync(0xFFFFFFFFu, s, o);
        if (lane >= o) s += n;
    }
    int base = 0;
    if (lane == 31) base = atomicAdd(&g_total, s);
    base = __shfl_sync(0xFFFFFFFFu, base, 31);
    int start = base + s - c;
    if (i < Nn) {
        g_start[i] = start;
        g_cursor[i] = start;
    }
}

// ---------------- scatter edges into grouped order ----------------
__global__ __launch_bounds__(256) void scatter(const int* __restrict__ src,
                                               const int* __restrict__ dst,
                                               const float* __restrict__ val) {
    int e = blockIdx.x * 256 + threadIdx.x;
    if (e >= NE) return;
    int d = dst[e];
    int p = atomicAdd(&g_cursor[d], 1);
    g_pedge[p] = make_int2(src[e], __float_as_int(val[e]));
}

// ---------------- GEMM1: xw = x @ W1  (50000x256 @ 256x64) ----------------
__global__ __launch_bounds__(256) void gemm1(const float* __restrict__ x,
                                             const float* __restrict__ W1) {
    __shared__ float xs[128][32];  // 16KB
    __shared__ float ws[32][64];   // 8KB
    int tid = threadIdx.x;
    int m0 = blockIdx.x * 128;
    int c  = tid & 63;       // output column 0..63
    int tg = tid >> 6;       // row group 0..3

    float acc[32];
#pragma unroll
    for (int i = 0; i < 32; i++) acc[i] = 0.f;

    for (int k0 = 0; k0 < NF; k0 += 32) {
#pragma unroll
        for (int p = 0; p < 4; p++) {
            int idx = tid + p * 256;
            int r   = idx >> 3;
            int kk  = (idx & 7) << 2;
            int row = m0 + r;
            float4 v = make_float4(0.f, 0.f, 0.f, 0.f);
            if (row < Nn)
                v = *reinterpret_cast<const float4*>(&x[(size_t)row * NF + k0 + kk]);
            *reinterpret_cast<float4*>(&xs[r][kk]) = v;
        }
#pragma unroll
        for (int p = 0; p < 2; p++) {
            int idx = tid + p * 256;
            int kk  = idx >> 4;
            int cc  = (idx & 15) << 2;
            float4 v = *reinterpret_cast<const float4*>(&W1[(size_t)(k0 + kk) * NH + cc]);
            *reinterpret_cast<float4*>(&ws[kk][cc]) = v;
        }
        __syncthreads();
#pragma unroll
        for (int k4 = 0; k4 < 32; k4 += 4) {
            float w0 = ws[k4 + 0][c];
            float w1 = ws[k4 + 1][c];
            float w2 = ws[k4 + 2][c];
            float w3 = ws[k4 + 3][c];
#pragma unroll
            for (int i = 0; i < 32; i++) {
                float4 xv = *reinterpret_cast<float4*>(&xs[tg * 32 + i][k4]);
                acc[i] += xv.x * w0 + xv.y * w1 + xv.z * w2 + xv.w * w3;
            }
        }
        __syncthreads();
    }
#pragma unroll
    for (int i = 0; i < 32; i++) {
        int row = m0 + tg * 32 + i;
        if (row < Nn) g_xw[(size_t)row * NH + c] = acc[i];
    }
}

// ---------------- SpMM1 gather: h[r] = sum_e val*xw[src]  (64 feats) ----------------
__global__ __launch_bounds__(256) void spmm1g() {
    int r = blockIdx.x * 8 + (threadIdx.x >> 5);
    if (r >= Nn) return;
    int lane = threadIdx.x & 31;
    int e0 = g_start[r], e1 = e0 + g_cnt[r];
    float ax = 0.f, ay = 0.f;
    for (int e = e0; e < e1; e++) {
        int2 ed = g_pedge[e];
        float v = __int_as_float(ed.y);
        float2 t = reinterpret_cast<const float2*>(&g_xw[(size_t)ed.x * NH])[lane];
        ax += v * t.x;
        ay += v * t.y;
    }
    reinterpret_cast<float2*>(&g_h[(size_t)r * NH])[lane] = make_float2(ax, ay);
}

// ------- GEMM2: hw = relu(h + b1) @ [W11|W12]  (50000x64 @ 64x80) -------
// 128 rows per block in 4 passes; weights loaded once per block.
__global__ __launch_bounds__(320) void gemm2(const float* __restrict__ b1,
                                             const float* __restrict__ W11,
                                             const float* __restrict__ W12) {
    __shared__ float hs[32][64];   // 8KB
    __shared__ float wt[80][68];   // transposed weights, padded (21.25KB)
    int tid = threadIdx.x;
    int r0 = blockIdx.x * 128;

    for (int idx = tid; idx < 64 * 80; idx += 320) {
        int k = idx / 80;
        int j = idx % 80;
        wt[j][k] = (j < NC) ? W11[(size_t)k * NC + j] : W12[(size_t)k * NC + (j - NC)];
    }
    int j  = tid % 80;
    int rg = tid / 80;  // 0..3

#pragma unroll
    for (int pass = 0; pass < 4; pass++) {
        int rbase = r0 + pass * 32;
        __syncthreads();
        for (int idx = tid; idx < 32 * 64; idx += 320) {
            int r = idx >> 6;
            int k = idx & 63;
            int row = rbase + r;
            float hv = 0.f;
            if (row < Nn) hv = g_h[(size_t)row * NH + k] + b1[k];
            hs[r][k] = fmaxf(hv, 0.f);
        }
        __syncthreads();

        float acc[8];
#pragma unroll
        for (int i = 0; i < 8; i++) acc[i] = 0.f;
#pragma unroll
        for (int k = 0; k < 64; k += 4) {
            float4 w4 = *reinterpret_cast<float4*>(&wt[j][k]);
#pragma unroll
            for (int i = 0; i < 8; i++) {
                float4 h4 = *reinterpret_cast<float4*>(&hs[rg * 8 + i][k]);
                acc[i] += h4.x * w4.x + h4.y * w4.y + h4.z * w4.z + h4.w * w4.w;
            }
        }
#pragma unroll
        for (int i = 0; i < 8; i++) {
            int row = rbase + rg * 8 + i;
            if (row < Nn) g_hw[(size_t)row * NHW + j] = acc[i];
        }
    }
}

// -- SpMM2 gather + finalize: z = eps*exp(logstd)+mean; out = log_softmax(z) --
__global__ __launch_bounds__(256) void spmm2fin(const float* __restrict__ eps,
                                                const float* __restrict__ b11,
                                                const float* __restrict__ b12,
                                                float* __restrict__ out) {
    __shared__ float zrow[8][80];
    int w = threadIdx.x >> 5;
    int lane = threadIdx.x & 31;
    int r = blockIdx.x * 8 + w;
    if (r >= Nn) return;

    int e0 = g_start[r], e1 = e0 + g_cnt[r];
    float ax = 0.f, ay = 0.f, bx = 0.f, by = 0.f;
    for (int e = e0; e < e1; e++) {
        int2 ed = g_pedge[e];
        float v = __int_as_float(ed.y);
        const float2* hr = reinterpret_cast<const float2*>(&g_hw[(size_t)ed.x * NHW]);
        float2 t = hr[lane];
        ax += v * t.x;
        ay += v * t.y;
        if (lane < 8) {
            float2 u = hr[32 + lane];
            bx += v * u.x;
            by += v * u.y;
        }
    }
    zrow[w][lane * 2 + 0] = ax;
    zrow[w][lane * 2 + 1] = ay;
    if (lane < 8) {
        zrow[w][64 + lane * 2 + 0] = bx;
        zrow[w][64 + lane * 2 + 1] = by;
    }
    __syncwarp();

    const float* zr = zrow[w];
    float mean0 = zr[lane] + b11[lane];
    float ls0   = zr[NC + lane] + b12[lane];
    float z0 = eps[(size_t)r * NC + lane] * expf(ls0) + mean0;
    float z1 = -CUDART_INF_F;
    if (lane < 8) {
        int jj = 32 + lane;
        float mean1 = zr[jj] + b11[jj];
        float ls1   = zr[NC + jj] + b12[jj];
        z1 = eps[(size_t)r * NC + jj] * expf(ls1) + mean1;
    }
    float mx = fmaxf(z0, z1);
#pragma unroll
    for (int o = 16; o > 0; o >>= 1)
        mx = fmaxf(mx, __shfl_xor_sync(0xFFFFFFFFu, mx, o));
    float sm = expf(z0 - mx) + ((lane < 8) ? expf(z1 - mx) : 0.f);
#pragma unroll
    for (int o = 16; o > 0; o >>= 1)
        sm += __shfl_xor_sync(0xFFFFFFFFu, sm, o);
    float lse = logf(sm) + mx;
    out[(size_t)r * NC + lane] = z0 - lse;
    if (lane < 8)
        out[(size_t)r * NC + 32 + lane] = z1 - lse;
}

extern "C" void kernel_launch(void* const* d_in, const int* in_sizes, int n_in,
                              void* d_out, int out_size) {
    const float* x    = (const float*)d_in[0];
    const int*   esrc = (const int*)d_in[1];
    const int*   edst = (const int*)d_in[2];
    const float* evl  = (const float*)d_in[3];
    const float* eps  = (const float*)d_in[4];
    const float* W1   = (const float*)d_in[5];
    const float* b1   = (const float*)d_in[6];
    const float* W11  = (const float*)d_in[7];
    const float* b11  = (const float*)d_in[8];
    const float* W12  = (const float*)d_in[9];
    const float* b12  = (const float*)d_in[10];
    float* out = (float*)d_out;

    zero_cnt<<<(Nn + 255) / 256, 256>>>();
    hist<<<(NE + 255) / 256, 256>>>(edst);
    assign_seg<<<(Nn + 255) / 256, 256>>>();
    scatter<<<(NE + 255) / 256, 256>>>(esrc, edst, evl);
    gemm1<<<(Nn + 127) / 128, 256>>>(x, W1);
    spmm1g<<<(Nn + 7) / 8, 256>>>();
    gemm2<<<(Nn + 127) / 128, 320>>>(b1, W11, W12);
    spmm2fin<<<(Nn + 7) / 8, 256>>>(eps, b11, b12, out);
}